// round 14
// baseline (speedup 1.0000x reference)
#include <cuda_runtime.h>
#include <cstddef>

typedef unsigned long long ull;

#define NB 64
#define NT 256
#define NIN 1024
#define NH 2048
#define NM 512
#define NROW (NB * NT)
#define NBLK 128
#define NTHR 512

// proj tile (64x256) smem layout (R6 proven)
#define SA_STRIDE 96
#define SB_STRIDE 288
#define SA_BUF 3072
#define SB_BUF 9216
// G tile (64x128, K=128 resident)
#define GA_STR 96
#define GB_STR 160
#define GB_OFF 12288
#define DYN_BYTES 131072

// ---------------- device scratch ----------------
__device__ float g_xp[(size_t)NROW * NH];       // x . W_in^T (no bias)
__device__ float g_X0[(size_t)NROW * 1536];     // Ŵ0 . (xp + bias0)
__device__ float g_aP[(size_t)NROW * NM];       // (xp+bias0) . P̃0
__device__ float g_h[2 * NB * NM];
__device__ float g_gp[(size_t)4 * NB * 3072];   // G split partials
__device__ float g_Ws[2ull * 1536 * NH];        // Ŵ (lnw-scaled gate+cell weights)
__device__ float g_PT[2ull * NM * NH];          // P̃^T
__device__ float g_Wcomp[2ull * 3072 * NM];     // [M | Wh | Q] composite
__device__ float g_bias0[NH];                   // b_in + 0.1 fb_b
__device__ float g_cs[2 * 1536];
__device__ float g_dv[2 * 1536];
__device__ float g_cv1[1536];                   // Ŵ1 . cbc
__device__ float g_fbadj[1536];                 // Ŵ0 . (0.1 fb_b)
__device__ float g_p1[2 * NM];                  // colsum P̃
__device__ float g_aP1c[NM];                    // cbc . P̃1
__device__ float g_c12[2];                      // Σcbc, Σcbc²
__device__ float g_A1[NROW];
__device__ float g_A2[NROW];
__device__ float g_A1z[NB];
__device__ float g_A2z[NB];
__device__ float g_dcoef[2 * NM];
__device__ unsigned g_cnt, g_sense;

// ---------------- f32x2 helpers ----------------
__device__ __forceinline__ void fma2(ull &d, ull a, ull b) {
    asm("fma.rn.f32x2 %0, %1, %2, %0;" : "+l"(d) : "l"(a), "l"(b));
}
__device__ __forceinline__ ull dup2(float x) {
    ull r; asm("mov.b64 %0, {%1, %1};" : "=l"(r) : "f"(x)); return r;
}
__device__ __forceinline__ float2 unp(ull v) {
    float2 r; asm("mov.b64 {%0, %1}, %2;" : "=f"(r.x), "=f"(r.y) : "l"(v)); return r;
}

// ---------------- atomic grid barrier (R6 proven) ----------------
__device__ __forceinline__ void gbar(unsigned &sense) {
    __syncthreads();
    if (threadIdx.x == 0) {
        sense ^= 1u;
        __threadfence();
        unsigned a = atomicAdd(&g_cnt, 1u);
        if (a == NBLK - 1u) {
            g_cnt = 0u;
            asm volatile("st.global.release.gpu.u32 [%0], %1;"
                         :: "l"(&g_sense), "r"(sense) : "memory");
        } else {
            unsigned s;
            do {
                asm volatile("ld.global.acquire.gpu.u32 %0, [%1];"
                             : "=r"(s) : "l"(&g_sense) : "memory");
            } while (s != sense);
        }
    }
    __syncthreads();
}

// ---------------- 64x256 proj tile inner (R6 proven) ----------------
__device__ __forceinline__ void mm_k32(ull acc[4][4], const float* sAb, const float* sBb,
                                       int r0, int c0) {
#pragma unroll 8
    for (int k = 0; k < 32; k++) {
        int rot = k & 28;
        const float* ar = sAb + k * SA_STRIDE + rot + r0;
        ull a0 = *(const ull*)(ar);
        ull a1 = *(const ull*)(ar + 2);
        ull a2 = *(const ull*)(ar + 4);
        ull a3 = *(const ull*)(ar + 6);
        float4 bf = *(const float4*)(sBb + k * SB_STRIDE + rot + c0);
        ull b0 = dup2(bf.x), b1 = dup2(bf.y), b2 = dup2(bf.z), b3 = dup2(bf.w);
        fma2(acc[0][0], a0, b0); fma2(acc[0][1], a0, b1); fma2(acc[0][2], a0, b2); fma2(acc[0][3], a0, b3);
        fma2(acc[1][0], a1, b0); fma2(acc[1][1], a1, b1); fma2(acc[1][2], a1, b2); fma2(acc[1][3], a1, b3);
        fma2(acc[2][0], a2, b0); fma2(acc[2][1], a2, b1); fma2(acc[2][2], a2, b2); fma2(acc[2][3], a2, b3);
        fma2(acc[3][0], a3, b0); fma2(acc[3][1], a3, b1); fma2(acc[3][2], a3, b2); fma2(acc[3][3], a3, b3);
    }
}

#define STORE_AB(bsel) do { \
    float* dA = sA + (bsel) * SA_BUF + (akq * 4) * SA_STRIDE + akq * 4 + arow; \
    dA[0] = ra.x; dA[SA_STRIDE] = ra.y; dA[2 * SA_STRIDE] = ra.z; dA[3 * SA_STRIDE] = ra.w; \
    _Pragma("unroll") \
    for (int i2 = 0; i2 < 4; i2++) { \
        float* dB = sB + (bsel) * SB_BUF + (bkq[i2] * 4) * SB_STRIDE + bkq[i2] * 4 + bcol[i2]; \
        dB[0] = rb[i2].x; dB[SB_STRIDE] = rb[i2].y; \
        dB[2 * SB_STRIDE] = rb[i2].z; dB[3 * SB_STRIDE] = rb[i2].w; \
    } \
} while (0)

__global__ void __launch_bounds__(NTHR)
ltc_all(const float* __restrict__ x,      const float* __restrict__ hidden,
        const float* __restrict__ W_in,   const float* __restrict__ b_in,
        const float* __restrict__ cell_W, const float* __restrict__ cell_b,
        const float* __restrict__ upd_W,  const float* __restrict__ upd_b,
        const float* __restrict__ rst_W,  const float* __restrict__ rst_b,
        const float* __restrict__ tau,
        const float* __restrict__ lc_W,   const float* __restrict__ lc_b,
        const float* __restrict__ sk_W,   const float* __restrict__ sk_b,
        const float* __restrict__ fb_W,   const float* __restrict__ fb_b,
        const float* __restrict__ ln_w,   const float* __restrict__ ln_b,
        const float* __restrict__ mn_w,   const float* __restrict__ mn_b,
        float* __restrict__ out)
{
    extern __shared__ float dyn[];
    float* sA  = dyn;                 // proj layout
    float* sB  = dyn + 2 * SA_BUF;
    float* gAs = dyn;                 // G layout
    float* gBs = dyn + GB_OFF;
    __shared__ float sRed[48];
    __shared__ float sOut[8];

    const int tid = threadIdx.x;
    const int bid = blockIdx.x;
    unsigned sense = *(volatile unsigned*)&g_sense;

    const int arow = tid >> 3, akq = tid & 7;
    int bcol[4], bkq[4];
#pragma unroll
    for (int i = 0; i < 4; i++) { int id = tid + i * NTHR; bcol[i] = id >> 3; bkq[i] = id & 7; }
    const int r0 = (tid >> 6) * 8;
    const int c0 = (tid & 63) * 4;

    const size_t gt = (size_t)bid * NTHR + tid;
    const size_t GS = (size_t)NBLK * NTHR;

    // ================= stage A: element-wise precompute + xp GEMM =================
    for (size_t i = gt; i < 2 * NB * NM; i += GS) g_h[i] = hidden[i];
    for (size_t i = gt; i < NH; i += GS) g_bias0[i] = b_in[i] + 0.1f * fb_b[i];
    for (size_t i = gt; i < 2 * NM; i += GS) {
        float tv = tau[i];
        float sp = (tv > 20.f) ? tv : log1pf(expf(tv));
        float tc = fminf(fmaxf(sp, 0.1f), 10.f);
        g_dcoef[i] = expf(-1.f / tc);
    }
    for (size_t i = gt; i < 2ull * 1536 * NH; i += GS) {
        size_t l = i / (1536ull * NH);
        size_t rem = i - l * 1536ull * NH;
        int j = (int)(rem / NH), h = (int)(rem % NH);
        float w = (j < 512)  ? upd_W[(l * 512 + j) * 2560 + h]
                : (j < 1024) ? rst_W[(l * 512 + (j - 512)) * 2560 + h]
                             : cell_W[(l * 512 + (j - 1024)) * (size_t)NH + h];
        g_Ws[i] = w * ln_w[l * NH + h];
    }
    for (size_t i = gt; i < 2ull * NH * NM; i += GS) {
        size_t l = i / ((size_t)NH * NM);
        size_t rem = i - l * (size_t)NH * NM;
        int h = (int)(rem / NM), m = (int)(rem % NM);
        float v = (l == 0) ? 0.1f * fb_W[(size_t)h * NM + m]
                           : sk_W[(size_t)h * NM + m] + lc_W[(size_t)h * NM + m];
        g_PT[l * (size_t)NM * NH + (size_t)m * NH + h] = v;
    }
    for (size_t i = gt; i < 2ull * 1024 * NM; i += GS) {
        size_t l = i / (1024ull * NM);
        size_t rem = i - l * 1024ull * NM;
        int jj = (int)(rem / NM), m = (int)(rem % NM);
        float w = (jj < 512) ? upd_W[(l * 512 + jj) * 2560 + 2048 + m]
                             : rst_W[(l * 512 + (jj - 512)) * 2560 + 2048 + m];
        g_Wcomp[l * 3072ull * NM + (size_t)(1536 + jj) * NM + m] = w;
    }
    if (gt < 2 * NM) {
        int l = (int)(gt / NM), m = (int)(gt % NM);
        float s = 0.f;
        for (int h = 0; h < NH; h++)
            s += (l == 0) ? 0.1f * fb_W[(size_t)h * NM + m]
                          : sk_W[(size_t)h * NM + m] + lc_W[(size_t)h * NM + m];
        g_p1[gt] = s;
    }
    if (gt < NM) {
        float s = 0.f;
        for (int h = 0; h < NH; h++)
            s += (sk_b[h] + lc_b[h]) * (sk_W[(size_t)h * NM + gt] + lc_W[(size_t)h * NM + gt]);
        g_aP1c[gt] = s;
    }
    if (gt == 0) {
        float s1 = 0.f, s2 = 0.f;
        for (int h = 0; h < NH; h++) { float c = sk_b[h] + lc_b[h]; s1 += c; s2 += c * c; }
        g_c12[0] = s1; g_c12[1] = s2;
    }
    if (gt < 4ull * 2 * 1536) {
        int q = (int)(gt & 3);
        int j4 = (int)(gt >> 2);
        int l = j4 / 1536, j = j4 % 1536;
        const float* rowp;
        float bias;
        if (j < 512)       { rowp = upd_W  + ((size_t)l * 512 + j) * 2560;          bias = upd_b[l * 512 + j]; }
        else if (j < 1024) { rowp = rst_W  + ((size_t)l * 512 + (j - 512)) * 2560;  bias = rst_b[l * 512 + j - 512]; }
        else               { rowp = cell_W + ((size_t)l * 512 + (j - 1024)) * (size_t)NH; bias = cell_b[l * 512 + j - 1024]; }
        float cs = 0.f, dvv = 0.f, aux = 0.f;
        for (int i = 0; i < 512; i++) {
            int h = q + 4 * i;
            float w = rowp[h];
            float lw = ln_w[l * NH + h], lb = ln_b[l * NH + h];
            cs += w * lw;
            dvv += w * lb;
            aux += (l == 0) ? w * lw * 0.1f * fb_b[h] : w * lw * (sk_b[h] + lc_b[h]);
        }
        cs  += __shfl_xor_sync(0xffffffffu, cs, 1);  cs  += __shfl_xor_sync(0xffffffffu, cs, 2);
        dvv += __shfl_xor_sync(0xffffffffu, dvv, 1); dvv += __shfl_xor_sync(0xffffffffu, dvv, 2);
        aux += __shfl_xor_sync(0xffffffffu, aux, 1); aux += __shfl_xor_sync(0xffffffffu, aux, 2);
        if (q == 0) {
            g_cs[j4] = cs;
            g_dv[j4] = dvv + bias;
            if (l == 0) g_fbadj[j] = aux; else g_cv1[j] = aux;
        }
    }

    // xp = x . W_in^T  (2048 tasks 64x256, K=1024)
    for (int p = 0; p < 16; p++) {
        int task = bid + p * NBLK;
        int rowBase = (task >> 3) * 64, colBase = (task & 7) * 256;
        ull acc[4][4];
#pragma unroll
        for (int i = 0; i < 4; i++)
#pragma unroll
            for (int j = 0; j < 4; j++) acc[i][j] = 0ull;
        float4 ra, rb[4];
        ra = *(const float4*)(x + (size_t)(rowBase + arow) * NIN + akq * 4);
#pragma unroll
        for (int i = 0; i < 4; i++)
            rb[i] = *(const float4*)(W_in + (size_t)(colBase + bcol[i]) * NIN + bkq[i] * 4);
        STORE_AB(0);
        __syncthreads();
        for (int ku = 0; ku < 32; ku++) {
            if (ku + 1 < 32) {
                int kc = (ku + 1) * 32;
                ra = *(const float4*)(x + (size_t)(rowBase + arow) * NIN + kc + akq * 4);
#pragma unroll
                for (int i = 0; i < 4; i++)
                    rb[i] = *(const float4*)(W_in + (size_t)(colBase + bcol[i]) * NIN + kc + bkq[i] * 4);
            }
            mm_k32(acc, sA + (ku & 1) * SA_BUF, sB + (ku & 1) * SB_BUF, r0, c0);
            if (ku + 1 < 32) STORE_AB((ku + 1) & 1);
            __syncthreads();
        }
#pragma unroll
        for (int rp = 0; rp < 4; rp++) {
            float2 p0 = unp(acc[rp][0]), p1 = unp(acc[rp][1]);
            float2 p2 = unp(acc[rp][2]), p3 = unp(acc[rp][3]);
            float4 lo = {p0.x, p1.x, p2.x, p3.x};
            float4 hi = {p0.y, p1.y, p2.y, p3.y};
            size_t rr = (size_t)rowBase + r0 + 2 * rp;
            *(float4*)(g_xp + rr * NH + colBase + c0) = lo;
            *(float4*)(g_xp + (rr + 1) * NH + colBase + c0) = hi;
        }
    }
    gbar(sense);

    // ================= stage B: derived GEMMs (2176 uniform 64x256xK2048 tasks) ====
    for (int p = 0; p < 17; p++) {
        int task = bid + p * NBLK;
        const float *Ap, *Bp;
        float* Cp;
        int ldc, rowBase, colBase, addb;
        if (task < 1536) {
            rowBase = (task / 6) * 64; colBase = (task % 6) * 256;
            Ap = g_xp; addb = 1; Bp = g_Ws; Cp = g_X0; ldc = 1536;
        } else if (task < 2048) {
            int tt = task - 1536;
            rowBase = (tt / 2) * 64; colBase = (tt % 2) * 256;
            Ap = g_xp; addb = 1; Bp = g_PT; Cp = g_aP; ldc = NM;
        } else if (task < 2080) {
            int tt = task - 2048; int l = tt / 16, q = tt % 16;
            rowBase = (q / 2) * 64; colBase = (q % 2) * 256;
            Ap = g_PT + (size_t)l * NM * NH; addb = 0;
            Bp = g_PT + (size_t)l * NM * NH;
            Cp = g_Wcomp + (size_t)l * 3072 * NM + 2560ull * NM; ldc = NM;
        } else {
            int tt = task - 2080; int l = tt / 48, q = tt % 48;
            rowBase = (q / 2) * 64; colBase = (q % 2) * 256;
            Ap = g_Ws + (size_t)l * 1536 * NH; addb = 0;
            Bp = g_PT + (size_t)l * NM * NH;
            Cp = g_Wcomp + (size_t)l * 3072 * NM; ldc = NM;
        }
        ull acc[4][4];
#pragma unroll
        for (int i = 0; i < 4; i++)
#pragma unroll
            for (int j = 0; j < 4; j++) acc[i][j] = 0ull;
        float4 ra, rb[4];
        {
            int kg = akq * 4;
            ra = *(const float4*)(Ap + (size_t)(rowBase + arow) * NH + kg);
            if (addb) {
                float4 bb = *(const float4*)(g_bias0 + kg);
                ra.x += bb.x; ra.y += bb.y; ra.z += bb.z; ra.w += bb.w;
            }
#pragma unroll
            for (int i = 0; i < 4; i++)
                rb[i] = *(const float4*)(Bp + (size_t)(colBase + bcol[i]) * NH + bkq[i] * 4);
        }
        STORE_AB(0);
        __syncthreads();
        for (int ku = 0; ku < 64; ku++) {
            if (ku + 1 < 64) {
                int kc = (ku + 1) * 32;
                int kg = kc + akq * 4;
                ra = *(const float4*)(Ap + (size_t)(rowBase + arow) * NH + kg);
                if (addb) {
                    float4 bb = *(const float4*)(g_bias0 + kg);
                    ra.x += bb.x; ra.y += bb.y; ra.z += bb.z; ra.w += bb.w;
                }
#pragma unroll
                for (int i = 0; i < 4; i++)
                    rb[i] = *(const float4*)(Bp + (size_t)(colBase + bcol[i]) * NH + kc + bkq[i] * 4);
            }
            mm_k32(acc, sA + (ku & 1) * SA_BUF, sB + (ku & 1) * SB_BUF, r0, c0);
            if (ku + 1 < 64) STORE_AB((ku + 1) & 1);
            __syncthreads();
        }
#pragma unroll
        for (int rp = 0; rp < 4; rp++) {
            float2 p0 = unp(acc[rp][0]), p1 = unp(acc[rp][1]);
            float2 p2 = unp(acc[rp][2]), p3 = unp(acc[rp][3]);
            float4 lo = {p0.x, p1.x, p2.x, p3.x};
            float4 hi = {p0.y, p1.y, p2.y, p3.y};
            size_t rr = (size_t)rowBase + r0 + 2 * rp;
            *(float4*)(Cp + rr * ldc + colBase + c0) = lo;
            *(float4*)(Cp + (rr + 1) * ldc + colBase + c0) = hi;
        }
    }
    // A1/A2 row stats (a = xp + bias0)
    {
        int q = tid & 3;
        int r = bid * 128 + (tid >> 2);
        float s1 = 0.f, s2 = 0.f;
        for (int i = 0; i < 512; i++) {
            int h = q + 4 * i;
            float a = g_xp[(size_t)r * NH + h] + g_bias0[h];
            s1 += a; s2 += a * a;
        }
        s1 += __shfl_xor_sync(0xffffffffu, s1, 1); s1 += __shfl_xor_sync(0xffffffffu, s1, 2);
        s2 += __shfl_xor_sync(0xffffffffu, s2, 1); s2 += __shfl_xor_sync(0xffffffffu, s2, 2);
        if (q == 0) { g_A1[r] = s1; g_A2[r] = s2; }
    }
    if (bid == 0 && tid < 256) {
        int q = tid & 3, b = tid >> 2;
        size_t base = (size_t)b * NT * NH;
        float s1 = 0.f, s2 = 0.f;
        for (int i = 0; i < 512; i++) {
            int h = q + 4 * i;
            float a = g_xp[base + h] + b_in[h];
            s1 += a; s2 += a * a;
        }
        s1 += __shfl_xor_sync(0xffffffffu, s1, 1); s1 += __shfl_xor_sync(0xffffffffu, s1, 2);
        s2 += __shfl_xor_sync(0xffffffffu, s2, 1); s2 += __shfl_xor_sync(0xffffffffu, s2, 2);
        if (q == 0) { g_A1z[b] = s1; g_A2z[b] = s2; }
    }
    gbar(sense);

    // ================= time loop =================
    for (int t = 0; t < NT; t++) {
        for (int l = 0; l < 2; l++) {
            const float* hoth = g_h + ((l == 0) ? NB * NM : 0);
            const float* hslf = g_h + ((l == 0) ? 0 : NB * NM);

            // ===== phase G: composite GEMM, 96 blocks x (64x128xK128) =====
            if (bid < 96) {
                int ct = bid >> 2, sp = bid & 3, kb = sp * 128;
                const float* Aop = (ct < 12 || ct >= 20) ? hoth : hslf;
                const float* Bop = g_Wcomp + (size_t)l * 3072 * NM + (size_t)(ct * 128) * NM;
                // loads
                float4 va[4], vb[8];
#pragma unroll
                for (int i = 0; i < 4; i++) {
                    int id = tid + i * NTHR;
                    va[i] = *(const float4*)(Aop + (size_t)(id >> 5) * NM + kb + (id & 31) * 4);
                }
#pragma unroll
                for (int i = 0; i < 8; i++) {
                    int id = tid + i * NTHR;
                    vb[i] = *(const float4*)(Bop + (size_t)(id >> 5) * NM + kb + (id & 31) * 4);
                }
#pragma unroll
                for (int i = 0; i < 4; i++) {
                    int id = tid + i * NTHR;
                    int row = id >> 5, kq = id & 31;
                    int rot = (kq * 4) & 28;
                    float* dA = gAs + (kq * 4) * GA_STR + rot + row;
                    dA[0] = va[i].x; dA[GA_STR] = va[i].y;
                    dA[2 * GA_STR] = va[i].z; dA[3 * GA_STR] = va[i].w;
                }
#pragma unroll
                for (int i = 0; i < 8; i++) {
                    int id = tid + i * NTHR;
                    int col = id >> 5, kq = id & 31;
                    int rot = (kq * 4) & 28;
                    float* dB = gBs + (kq * 4) * GB_STR + rot + col;
                    dB[0] = vb[i].x; dB[GB_STR] = vb[i].y;
                    dB[2 * GB_STR] = vb[i].z; dB[3 * GB_STR] = vb[i].w;
                }
                __syncthreads();
                const int gr0 = (tid >> 6) * 8;
                const int gc0 = (tid & 63) * 2;
                ull acc[4][2];
#pragma unroll
                for (int i = 0; i < 4; i++) { acc[i][0] = 0ull; acc[i][1] = 0ull; }
#pragma unroll 8
                for (int k = 0; k < 128; k++) {
                    int rot = k & 28;
                    const float* ar = gAs + k * GA_STR + rot + gr0;
                    ull a0 = *(const ull*)(ar);
                    ull a1 = *(const ull*)(ar + 2);
                    ull a2 = *(const ull*)(ar + 4);
                    ull a3 = *(const ull*)(ar + 6);
                    float2 bf = *(const float2*)(gBs + k * GB_STR + rot + gc0);
                    ull b0 = dup2(bf.x), b1 = dup2(bf.y);
                    fma2(acc[0][0], a0, b0); fma2(acc[0][1], a0, b1);
                    fma2(acc[1][0], a1, b0); fma2(acc[1][1], a1, b1);
                    fma2(acc[2][0], a2, b0); fma2(acc[2][1], a2, b1);
                    fma2(acc[3][0], a3, b0); fma2(acc[3][1], a3, b1);
                }
#pragma unroll
                for (int rp = 0; rp < 4; rp++) {
                    float2 v0 = unp(acc[rp][0]), v1 = unp(acc[rp][1]);
                    int row = gr0 + 2 * rp;
                    *(float2*)(g_gp + (size_t)(sp * NB + row) * 3072 + ct * 128 + gc0) =
                        make_float2(v0.x, v1.x);
                    *(float2*)(g_gp + (size_t)(sp * NB + row + 1) * 3072 + ct * 128 + gc0) =
                        make_float2(v0.y, v1.y);
                }
            }
            gbar(sense);

            // ===== phase C: stats assembly + gates + mem-LN =====
            if (bid < NB) {
                int b = bid, m = tid;
                float gs[6];
#pragma unroll
                for (int c = 0; c < 6; c++) {
                    float s = 0.f;
#pragma unroll
                    for (int sp = 0; sp < 4; sp++)
                        s += g_gp[(size_t)(sp * NB + b) * 3072 + c * 512 + m];
                    gs[c] = s;
                }
                float ho = hoth[b * NM + m];
                float hs = hslf[b * NM + m];
                float ph  = g_p1[l * NM + m] * ho;
                float aph = ((l == 0) ? g_aP[((size_t)b * NT + t) * NM + m] : g_aP1c[m]) * ho;
                float hqh = gs[5] * ho;
#pragma unroll
                for (int off = 16; off > 0; off >>= 1) {
                    ph  += __shfl_xor_sync(0xffffffffu, ph, off);
                    aph += __shfl_xor_sync(0xffffffffu, aph, off);
                    hqh += __shfl_xor_sync(0xffffffffu, hqh, off);
                }
                int w = tid >> 5;
                if ((tid & 31) == 0) { sRed[w] = ph; sRed[16 + w] = aph; sRed[32 + w] = hqh; }
                __syncthreads();
                if (tid == 0) {
                    float t0 = 0.f, t1 = 0.f, t2 = 0.f;
#pragma unroll
                    for (int i = 0; i < 16; i++) { t0 += sRed[i]; t1 += sRed[16 + i]; t2 += sRed[32 + i]; }
                    sOut[0] = t0; sOut[1] = t1; sOut[2] = t2;
                }
                __syncthreads();
                float S1, S2, fbf = 1.f;
                if (l == 0) {
                    if (t == 0) { S1 = g_A1z[b]; S2 = g_A2z[b]; fbf = 0.f; }
                    else {
                        S1 = g_A1[(size_t)b * NT + t] + sOut[0];
                        S2 = g_A2[(size_t)b * NT + t] + 2.f * sOut[1] + sOut[2];
                    }
                } else {
                    S1 = g_c12[0] + sOut[0];
                    S2 = g_c12[1] + 2.f * sOut[1] + sOut[2];
                }
                float mu = S1 * (1.f / NH);
                float ri = rsqrtf(S2 * (1.f / NH) - mu * mu + 1e-5f);
                float Xu, Xr, Xc;
                if (l == 0) {
                    const float* xb = g_X0 + ((size_t)b * NT + t) * 1536;
                    Xu = xb[m]; Xr = xb[512 + m]; Xc = xb[1024 + m];
                    if (t == 0) { Xu -= g_fbadj[m]; Xr -= g_fbadj[512 + m]; Xc -= g_fbadj[1024 + m]; }
                } else {
                    Xu = g_cv1[m]; Xr = g_cv1[512 + m]; Xc = g_cv1[1024 + m];
                }
                int cb = l * 1536;
                float pu = ri * (Xu + fbf * gs[0] - mu * g_cs[cb + m])        + g_dv[cb + m]        + gs[3];
                float pr = ri * (Xr + fbf * gs[1] - mu * g_cs[cb + 512 + m])  + g_dv[cb + 512 + m]  + gs[4];
                float pc = ri * (Xc + fbf * gs[2] - mu * g_cs[cb + 1024 + m]) + g_dv[cb + 1024 + m];
                float u = 1.f / (1.f + expf(-pu));
                float r = 1.f / (1.f + expf(-pr));
                float cand = tanhf(pc);
                float d = g_dcoef[l * NM + m] * u;
                float hn = d * (hs * r) + (1.f - d) * cand;
                float s1 = hn, s2 = hn * hn;
#pragma unroll
                for (int off = 16; off > 0; off >>= 1) {
                    s1 += __shfl_xor_sync(0xffffffffu, s1, off);
                    s2 += __shfl_xor_sync(0xffffffffu, s2, off);
                }
                if ((tid & 31) == 0) { sRed[w] = s1; sRed[16 + w] = s2; }
                __syncthreads();
                if (tid == 0) {
                    float t1 = 0.f, t2 = 0.f;
#pragma unroll
                    for (int i = 0; i < 16; i++) { t1 += sRed[i]; t2 += sRed[16 + i]; }
                    float mu2 = t1 * (1.f / NM);
                    sOut[3] = mu2;
                    sOut[4] = rsqrtf(t2 * (1.f / NM) - mu2 * mu2 + 1e-5f);
                }
                __syncthreads();
                float vv = (hn - sOut[3]) * sOut[4] * mn_w[l * NM + m] + mn_b[l * NM + m];
                g_h[(size_t)(l * NB + b) * NM + m] = vv;
                if (l == 1) out[((size_t)b * NT + t) * NM + m] = vv;
            }
            gbar(sense);
        }
    }

    // ---- final hidden states hT appended after outs [B,T,M] ----
    for (int i = bid * NTHR + tid; i < 2 * NB * NM; i += NBLK * NTHR)
        out[(size_t)NB * NT * NM + i] = g_h[i];
}

extern "C" void kernel_launch(void* const* d_in, const int* in_sizes, int n_in,
                              void* d_out, int out_size)
{
    const float* x      = (const float*)d_in[0];
    const float* hidden = (const float*)d_in[1];
    const float* W_in   = (const float*)d_in[2];
    const float* b_in   = (const float*)d_in[3];
    const float* cell_W = (const float*)d_in[4];
    const float* cell_b = (const float*)d_in[5];
    const float* upd_W  = (const float*)d_in[6];
    const float* upd_b  = (const float*)d_in[7];
    const float* rst_W  = (const float*)d_in[8];
    const float* rst_b  = (const float*)d_in[9];
    const float* tau    = (const float*)d_in[10];
    const float* lc_W   = (const float*)d_in[11];
    const float* lc_b   = (const float*)d_in[12];
    const float* sk_W   = (const float*)d_in[13];
    const float* sk_b   = (const float*)d_in[14];
    const float* fb_W   = (const float*)d_in[15];
    const float* fb_b   = (const float*)d_in[16];
    const float* ln_w   = (const float*)d_in[17];
    const float* ln_b   = (const float*)d_in[18];
    const float* mn_w   = (const float*)d_in[19];
    const float* mn_b   = (const float*)d_in[20];
    float* out = (float*)d_out;

    cudaFuncSetAttribute(ltc_all, cudaFuncAttributeMaxDynamicSharedMemorySize, DYN_BYTES);
    ltc_all<<<NBLK, NTHR, DYN_BYTES>>>(x, hidden, W_in, b_in, cell_W, cell_b,
                                       upd_W, upd_b, rst_W, rst_b, tau,
                                       lc_W, lc_b, sk_W, sk_b, fb_W, fb_b,
                                       ln_w, ln_b, mn_w, mn_b, out);
}

// round 15
// speedup vs baseline: 1.0035x; 1.0035x over previous
#include <cuda_runtime.h>
#include <cstddef>

typedef unsigned long long ull;

#define NB 64
#define NT 256
#define NIN 1024
#define NH 2048
#define NM 512
#define NROW (NB * NT)
#define NBLK 128
#define NTHR 512

// proj tile (64x256) smem layout (R6 proven)
#define SA_STRIDE 96
#define SB_STRIDE 288
#define SA_BUF 3072
#define SB_BUF 9216
// G tile (64x128, K=128 resident)
#define GA_STR 96
#define GB_STR 160
#define GB_OFF 12288
#define DYN_BYTES 131072

// ---------------- device scratch ----------------
__device__ float g_xp[(size_t)NROW * NH];       // x . W_in^T (no bias)
__device__ float g_X0[(size_t)NROW * 1536];     // Ŵ0 . (xp + bias0)
__device__ float g_aP[(size_t)NROW * NM];       // (xp+bias0) . P̃0
__device__ float g_h[2 * NB * NM];
__device__ float g_gp[(size_t)4 * NB * 3072];   // G split partials
__device__ float g_Ws[2ull * 1536 * NH];        // Ŵ (lnw-scaled gate+cell weights)
__device__ float g_PT[2ull * NM * NH];          // P̃^T
__device__ float g_Wcomp[2ull * 3072 * NM];     // [M | Wh | Q] composite
__device__ float g_bias0[NH];                   // b_in + 0.1 fb_b
__device__ float g_cs[2 * 1536];
__device__ float g_dv[2 * 1536];
__device__ float g_cv1[1536];                   // Ŵ1 . cbc
__device__ float g_fbadj[1536];                 // Ŵ0 . (0.1 fb_b)
__device__ float g_p1[2 * NM];                  // colsum P̃
__device__ float g_aP1c[NM];                    // cbc . P̃1
__device__ float g_c12[2];                      // Σcbc, Σcbc²
__device__ float g_A1[NROW];
__device__ float g_A2[NROW];
__device__ float g_A1z[NB];
__device__ float g_A2z[NB];
__device__ float g_dcoef[2 * NM];
__device__ unsigned g_cnt, g_sense;

// ---------------- f32x2 helpers ----------------
__device__ __forceinline__ void fma2(ull &d, ull a, ull b) {
    asm("fma.rn.f32x2 %0, %1, %2, %0;" : "+l"(d) : "l"(a), "l"(b));
}
__device__ __forceinline__ ull dup2(float x) {
    ull r; asm("mov.b64 %0, {%1, %1};" : "=l"(r) : "f"(x)); return r;
}
__device__ __forceinline__ float2 unp(ull v) {
    float2 r; asm("mov.b64 {%0, %1}, %2;" : "=f"(r.x), "=f"(r.y) : "l"(v)); return r;
}

// ---------------- atomic grid barrier (R6 proven) ----------------
__device__ __forceinline__ void gbar(unsigned &sense) {
    __syncthreads();
    if (threadIdx.x == 0) {
        sense ^= 1u;
        __threadfence();
        unsigned a = atomicAdd(&g_cnt, 1u);
        if (a == NBLK - 1u) {
            g_cnt = 0u;
            asm volatile("st.global.release.gpu.u32 [%0], %1;"
                         :: "l"(&g_sense), "r"(sense) : "memory");
        } else {
            unsigned s;
            do {
                asm volatile("ld.global.acquire.gpu.u32 %0, [%1];"
                             : "=r"(s) : "l"(&g_sense) : "memory");
            } while (s != sense);
        }
    }
    __syncthreads();
}

// ---------------- 64x256 proj tile inner (R6 proven) ----------------
__device__ __forceinline__ void mm_k32(ull acc[4][4], const float* sAb, const float* sBb,
                                       int r0, int c0) {
#pragma unroll 8
    for (int k = 0; k < 32; k++) {
        int rot = k & 28;
        const float* ar = sAb + k * SA_STRIDE + rot + r0;
        ull a0 = *(const ull*)(ar);
        ull a1 = *(const ull*)(ar + 2);
        ull a2 = *(const ull*)(ar + 4);
        ull a3 = *(const ull*)(ar + 6);
        float4 bf = *(const float4*)(sBb + k * SB_STRIDE + rot + c0);
        ull b0 = dup2(bf.x), b1 = dup2(bf.y), b2 = dup2(bf.z), b3 = dup2(bf.w);
        fma2(acc[0][0], a0, b0); fma2(acc[0][1], a0, b1); fma2(acc[0][2], a0, b2); fma2(acc[0][3], a0, b3);
        fma2(acc[1][0], a1, b0); fma2(acc[1][1], a1, b1); fma2(acc[1][2], a1, b2); fma2(acc[1][3], a1, b3);
        fma2(acc[2][0], a2, b0); fma2(acc[2][1], a2, b1); fma2(acc[2][2], a2, b2); fma2(acc[2][3], a2, b3);
        fma2(acc[3][0], a3, b0); fma2(acc[3][1], a3, b1); fma2(acc[3][2], a3, b2); fma2(acc[3][3], a3, b3);
    }
}

#define STORE_AB(bsel) do { \
    float* dA = sA + (bsel) * SA_BUF + (akq * 4) * SA_STRIDE + akq * 4 + arow; \
    dA[0] = ra.x; dA[SA_STRIDE] = ra.y; dA[2 * SA_STRIDE] = ra.z; dA[3 * SA_STRIDE] = ra.w; \
    _Pragma("unroll") \
    for (int i2 = 0; i2 < 4; i2++) { \
        float* dB = sB + (bsel) * SB_BUF + (bkq[i2] * 4) * SB_STRIDE + bkq[i2] * 4 + bcol[i2]; \
        dB[0] = rb[i2].x; dB[SB_STRIDE] = rb[i2].y; \
        dB[2 * SB_STRIDE] = rb[i2].z; dB[3 * SB_STRIDE] = rb[i2].w; \
    } \
} while (0)

__global__ void __launch_bounds__(NTHR)
ltc_all(const float* __restrict__ x,      const float* __restrict__ hidden,
        const float* __restrict__ W_in,   const float* __restrict__ b_in,
        const float* __restrict__ cell_W, const float* __restrict__ cell_b,
        const float* __restrict__ upd_W,  const float* __restrict__ upd_b,
        const float* __restrict__ rst_W,  const float* __restrict__ rst_b,
        const float* __restrict__ tau,
        const float* __restrict__ lc_W,   const float* __restrict__ lc_b,
        const float* __restrict__ sk_W,   const float* __restrict__ sk_b,
        const float* __restrict__ fb_W,   const float* __restrict__ fb_b,
        const float* __restrict__ ln_w,   const float* __restrict__ ln_b,
        const float* __restrict__ mn_w,   const float* __restrict__ mn_b,
        float* __restrict__ out)
{
    extern __shared__ float dyn[];
    float* sA  = dyn;                 // proj layout
    float* sB  = dyn + 2 * SA_BUF;
    float* gAs = dyn;                 // G layout
    float* gBs = dyn + GB_OFF;
    __shared__ float sRed[48];
    __shared__ float sOut[8];

    const int tid = threadIdx.x;
    const int bid = blockIdx.x;
    unsigned sense = *(volatile unsigned*)&g_sense;

    const int arow = tid >> 3, akq = tid & 7;
    int bcol[4], bkq[4];
#pragma unroll
    for (int i = 0; i < 4; i++) { int id = tid + i * NTHR; bcol[i] = id >> 3; bkq[i] = id & 7; }
    const int r0 = (tid >> 6) * 8;
    const int c0 = (tid & 63) * 4;

    const size_t gt = (size_t)bid * NTHR + tid;
    const size_t GS = (size_t)NBLK * NTHR;

    // ================= stage A: element-wise precompute + xp GEMM =================
    for (size_t i = gt; i < 2 * NB * NM; i += GS) g_h[i] = hidden[i];
    for (size_t i = gt; i < NH; i += GS) g_bias0[i] = b_in[i] + 0.1f * fb_b[i];
    for (size_t i = gt; i < 2 * NM; i += GS) {
        float tv = tau[i];
        float sp = (tv > 20.f) ? tv : log1pf(expf(tv));
        float tc = fminf(fmaxf(sp, 0.1f), 10.f);
        g_dcoef[i] = expf(-1.f / tc);
    }
    for (size_t i = gt; i < 2ull * 1536 * NH; i += GS) {
        size_t l = i / (1536ull * NH);
        size_t rem = i - l * 1536ull * NH;
        int j = (int)(rem / NH), h = (int)(rem % NH);
        float w = (j < 512)  ? upd_W[(l * 512 + j) * 2560 + h]
                : (j < 1024) ? rst_W[(l * 512 + (j - 512)) * 2560 + h]
                             : cell_W[(l * 512 + (j - 1024)) * (size_t)NH + h];
        g_Ws[i] = w * ln_w[l * NH + h];
    }
    for (size_t i = gt; i < 2ull * NH * NM; i += GS) {
        size_t l = i / ((size_t)NH * NM);
        size_t rem = i - l * (size_t)NH * NM;
        int h = (int)(rem / NM), m = (int)(rem % NM);
        float v = (l == 0) ? 0.1f * fb_W[(size_t)h * NM + m]
                           : sk_W[(size_t)h * NM + m] + lc_W[(size_t)h * NM + m];
        g_PT[l * (size_t)NM * NH + (size_t)m * NH + h] = v;
    }
    for (size_t i = gt; i < 2ull * 1024 * NM; i += GS) {
        size_t l = i / (1024ull * NM);
        size_t rem = i - l * 1024ull * NM;
        int jj = (int)(rem / NM), m = (int)(rem % NM);
        float w = (jj < 512) ? upd_W[(l * 512 + jj) * 2560 + 2048 + m]
                             : rst_W[(l * 512 + (jj - 512)) * 2560 + 2048 + m];
        g_Wcomp[l * 3072ull * NM + (size_t)(1536 + jj) * NM + m] = w;
    }
    if (gt < 2 * NM) {
        int l = (int)(gt / NM), m = (int)(gt % NM);
        float s = 0.f;
        for (int h = 0; h < NH; h++)
            s += (l == 0) ? 0.1f * fb_W[(size_t)h * NM + m]
                          : sk_W[(size_t)h * NM + m] + lc_W[(size_t)h * NM + m];
        g_p1[gt] = s;
    }
    if (gt < NM) {
        float s = 0.f;
        for (int h = 0; h < NH; h++)
            s += (sk_b[h] + lc_b[h]) * (sk_W[(size_t)h * NM + gt] + lc_W[(size_t)h * NM + gt]);
        g_aP1c[gt] = s;
    }
    if (gt == 0) {
        float s1 = 0.f, s2 = 0.f;
        for (int h = 0; h < NH; h++) { float c = sk_b[h] + lc_b[h]; s1 += c; s2 += c * c; }
        g_c12[0] = s1; g_c12[1] = s2;
    }
    if (gt < 4ull * 2 * 1536) {
        int q = (int)(gt & 3);
        int j4 = (int)(gt >> 2);
        int l = j4 / 1536, j = j4 % 1536;
        const float* rowp;
        float bias;
        if (j < 512)       { rowp = upd_W  + ((size_t)l * 512 + j) * 2560;          bias = upd_b[l * 512 + j]; }
        else if (j < 1024) { rowp = rst_W  + ((size_t)l * 512 + (j - 512)) * 2560;  bias = rst_b[l * 512 + j - 512]; }
        else               { rowp = cell_W + ((size_t)l * 512 + (j - 1024)) * (size_t)NH; bias = cell_b[l * 512 + j - 1024]; }
        float cs = 0.f, dvv = 0.f, aux = 0.f;
        for (int i = 0; i < 512; i++) {
            int h = q + 4 * i;
            float w = rowp[h];
            float lw = ln_w[l * NH + h], lb = ln_b[l * NH + h];
            cs += w * lw;
            dvv += w * lb;
            aux += (l == 0) ? w * lw * 0.1f * fb_b[h] : w * lw * (sk_b[h] + lc_b[h]);
        }
        cs  += __shfl_xor_sync(0xffffffffu, cs, 1);  cs  += __shfl_xor_sync(0xffffffffu, cs, 2);
        dvv += __shfl_xor_sync(0xffffffffu, dvv, 1); dvv += __shfl_xor_sync(0xffffffffu, dvv, 2);
        aux += __shfl_xor_sync(0xffffffffu, aux, 1); aux += __shfl_xor_sync(0xffffffffu, aux, 2);
        if (q == 0) {
            g_cs[j4] = cs;
            g_dv[j4] = dvv + bias;
            if (l == 0) g_fbadj[j] = aux; else g_cv1[j] = aux;
        }
    }

    // xp = x . W_in^T  (2048 tasks 64x256, K=1024)
    for (int p = 0; p < 16; p++) {
        int task = bid + p * NBLK;
        int rowBase = (task >> 3) * 64, colBase = (task & 7) * 256;
        ull acc[4][4];
#pragma unroll
        for (int i = 0; i < 4; i++)
#pragma unroll
            for (int j = 0; j < 4; j++) acc[i][j] = 0ull;
        float4 ra, rb[4];
        ra = *(const float4*)(x + (size_t)(rowBase + arow) * NIN + akq * 4);
#pragma unroll
        for (int i = 0; i < 4; i++)
            rb[i] = *(const float4*)(W_in + (size_t)(colBase + bcol[i]) * NIN + bkq[i] * 4);
        STORE_AB(0);
        __syncthreads();
        for (int ku = 0; ku < 32; ku++) {
            if (ku + 1 < 32) {
                int kc = (ku + 1) * 32;
                ra = *(const float4*)(x + (size_t)(rowBase + arow) * NIN + kc + akq * 4);
#pragma unroll
                for (int i = 0; i < 4; i++)
                    rb[i] = *(const float4*)(W_in + (size_t)(colBase + bcol[i]) * NIN + kc + bkq[i] * 4);
            }
            mm_k32(acc, sA + (ku & 1) * SA_BUF, sB + (ku & 1) * SB_BUF, r0, c0);
            if (ku + 1 < 32) STORE_AB((ku + 1) & 1);
            __syncthreads();
        }
#pragma unroll
        for (int rp = 0; rp < 4; rp++) {
            float2 p0 = unp(acc[rp][0]), p1 = unp(acc[rp][1]);
            float2 p2 = unp(acc[rp][2]), p3 = unp(acc[rp][3]);
            float4 lo = {p0.x, p1.x, p2.x, p3.x};
            float4 hi = {p0.y, p1.y, p2.y, p3.y};
            size_t rr = (size_t)rowBase + r0 + 2 * rp;
            *(float4*)(g_xp + rr * NH + colBase + c0) = lo;
            *(float4*)(g_xp + (rr + 1) * NH + colBase + c0) = hi;
        }
    }
    gbar(sense);

    // ================= stage B: derived GEMMs (2176 uniform 64x256xK2048 tasks) ====
    for (int p = 0; p < 17; p++) {
        int task = bid + p * NBLK;
        const float *Ap, *Bp;
        float* Cp;
        int ldc, rowBase, colBase, addb;
        if (task < 1536) {
            rowBase = (task / 6) * 64; colBase = (task % 6) * 256;
            Ap = g_xp; addb = 1; Bp = g_Ws; Cp = g_X0; ldc = 1536;
        } else if (task < 2048) {
            int tt = task - 1536;
            rowBase = (tt / 2) * 64; colBase = (tt % 2) * 256;
            Ap = g_xp; addb = 1; Bp = g_PT; Cp = g_aP; ldc = NM;
        } else if (task < 2080) {
            int tt = task - 2048; int l = tt / 16, q = tt % 16;
            rowBase = (q / 2) * 64; colBase = (q % 2) * 256;
            Ap = g_PT + (size_t)l * NM * NH; addb = 0;
            Bp = g_PT + (size_t)l * NM * NH;
            Cp = g_Wcomp + (size_t)l * 3072 * NM + 2560ull * NM; ldc = NM;
        } else {
            int tt = task - 2080; int l = tt / 48, q = tt % 48;
            rowBase = (q / 2) * 64; colBase = (q % 2) * 256;
            Ap = g_Ws + (size_t)l * 1536 * NH; addb = 0;
            Bp = g_PT + (size_t)l * NM * NH;
            Cp = g_Wcomp + (size_t)l * 3072 * NM; ldc = NM;
        }
        ull acc[4][4];
#pragma unroll
        for (int i = 0; i < 4; i++)
#pragma unroll
            for (int j = 0; j < 4; j++) acc[i][j] = 0ull;
        float4 ra, rb[4];
        {
            int kg = akq * 4;
            ra = *(const float4*)(Ap + (size_t)(rowBase + arow) * NH + kg);
            if (addb) {
                float4 bb = *(const float4*)(g_bias0 + kg);
                ra.x += bb.x; ra.y += bb.y; ra.z += bb.z; ra.w += bb.w;
            }
#pragma unroll
            for (int i = 0; i < 4; i++)
                rb[i] = *(const float4*)(Bp + (size_t)(colBase + bcol[i]) * NH + bkq[i] * 4);
        }
        STORE_AB(0);
        __syncthreads();
        for (int ku = 0; ku < 64; ku++) {
            if (ku + 1 < 64) {
                int kc = (ku + 1) * 32;
                int kg = kc + akq * 4;
                ra = *(const float4*)(Ap + (size_t)(rowBase + arow) * NH + kg);
                if (addb) {
                    float4 bb = *(const float4*)(g_bias0 + kg);
                    ra.x += bb.x; ra.y += bb.y; ra.z += bb.z; ra.w += bb.w;
                }
#pragma unroll
                for (int i = 0; i < 4; i++)
                    rb[i] = *(const float4*)(Bp + (size_t)(colBase + bcol[i]) * NH + kc + bkq[i] * 4);
            }
            mm_k32(acc, sA + (ku & 1) * SA_BUF, sB + (ku & 1) * SB_BUF, r0, c0);
            if (ku + 1 < 64) STORE_AB((ku + 1) & 1);
            __syncthreads();
        }
#pragma unroll
        for (int rp = 0; rp < 4; rp++) {
            float2 p0 = unp(acc[rp][0]), p1 = unp(acc[rp][1]);
            float2 p2 = unp(acc[rp][2]), p3 = unp(acc[rp][3]);
            float4 lo = {p0.x, p1.x, p2.x, p3.x};
            float4 hi = {p0.y, p1.y, p2.y, p3.y};
            size_t rr = (size_t)rowBase + r0 + 2 * rp;
            *(float4*)(Cp + rr * ldc + colBase + c0) = lo;
            *(float4*)(Cp + (rr + 1) * ldc + colBase + c0) = hi;
        }
    }
    // A1/A2 row stats (a = xp + bias0)
    {
        int q = tid & 3;
        int r = bid * 128 + (tid >> 2);
        float s1 = 0.f, s2 = 0.f;
        for (int i = 0; i < 512; i++) {
            int h = q + 4 * i;
            float a = g_xp[(size_t)r * NH + h] + g_bias0[h];
            s1 += a; s2 += a * a;
        }
        s1 += __shfl_xor_sync(0xffffffffu, s1, 1); s1 += __shfl_xor_sync(0xffffffffu, s1, 2);
        s2 += __shfl_xor_sync(0xffffffffu, s2, 1); s2 += __shfl_xor_sync(0xffffffffu, s2, 2);
        if (q == 0) { g_A1[r] = s1; g_A2[r] = s2; }
    }
    if (bid == 0 && tid < 256) {
        int q = tid & 3, b = tid >> 2;
        size_t base = (size_t)b * NT * NH;
        float s1 = 0.f, s2 = 0.f;
        for (int i = 0; i < 512; i++) {
            int h = q + 4 * i;
            float a = g_xp[base + h] + b_in[h];
            s1 += a; s2 += a * a;
        }
        s1 += __shfl_xor_sync(0xffffffffu, s1, 1); s1 += __shfl_xor_sync(0xffffffffu, s1, 2);
        s2 += __shfl_xor_sync(0xffffffffu, s2, 1); s2 += __shfl_xor_sync(0xffffffffu, s2, 2);
        if (q == 0) { g_A1z[b] = s1; g_A2z[b] = s2; }
    }
    gbar(sense);

    // ================= time loop =================
    for (int t = 0; t < NT; t++) {
        for (int l = 0; l < 2; l++) {
            const float* hoth = g_h + ((l == 0) ? NB * NM : 0);
            const float* hslf = g_h + ((l == 0) ? 0 : NB * NM);

            // ===== phase G: composite GEMM, 96 blocks x (64x128xK128) =====
            if (bid < 96) {
                int ct = bid >> 2, sp = bid & 3, kb = sp * 128;
                const float* Aop = (ct < 12 || ct >= 20) ? hoth : hslf;
                const float* Bop = g_Wcomp + (size_t)l * 3072 * NM + (size_t)(ct * 128) * NM;
                // loads
                float4 va[4], vb[8];
#pragma unroll
                for (int i = 0; i < 4; i++) {
                    int id = tid + i * NTHR;
                    va[i] = *(const float4*)(Aop + (size_t)(id >> 5) * NM + kb + (id & 31) * 4);
                }
#pragma unroll
                for (int i = 0; i < 8; i++) {
                    int id = tid + i * NTHR;
                    vb[i] = *(const float4*)(Bop + (size_t)(id >> 5) * NM + kb + (id & 31) * 4);
                }
#pragma unroll
                for (int i = 0; i < 4; i++) {
                    int id = tid + i * NTHR;
                    int row = id >> 5, kq = id & 31;
                    int rot = (kq * 4) & 28;
                    float* dA = gAs + (kq * 4) * GA_STR + rot + row;
                    dA[0] = va[i].x; dA[GA_STR] = va[i].y;
                    dA[2 * GA_STR] = va[i].z; dA[3 * GA_STR] = va[i].w;
                }
#pragma unroll
                for (int i = 0; i < 8; i++) {
                    int id = tid + i * NTHR;
                    int col = id >> 5, kq = id & 31;
                    int rot = (kq * 4) & 28;
                    float* dB = gBs + (kq * 4) * GB_STR + rot + col;
                    dB[0] = vb[i].x; dB[GB_STR] = vb[i].y;
                    dB[2 * GB_STR] = vb[i].z; dB[3 * GB_STR] = vb[i].w;
                }
                __syncthreads();
                const int gr0 = (tid >> 6) * 8;
                const int gc0 = (tid & 63) * 2;
                ull acc[4][2];
#pragma unroll
                for (int i = 0; i < 4; i++) { acc[i][0] = 0ull; acc[i][1] = 0ull; }
#pragma unroll 8
                for (int k = 0; k < 128; k++) {
                    int rot = k & 28;
                    const float* ar = gAs + k * GA_STR + rot + gr0;
                    ull a0 = *(const ull*)(ar);
                    ull a1 = *(const ull*)(ar + 2);
                    ull a2 = *(const ull*)(ar + 4);
                    ull a3 = *(const ull*)(ar + 6);
                    float2 bf = *(const float2*)(gBs + k * GB_STR + rot + gc0);
                    ull b0 = dup2(bf.x), b1 = dup2(bf.y);
                    fma2(acc[0][0], a0, b0); fma2(acc[0][1], a0, b1);
                    fma2(acc[1][0], a1, b0); fma2(acc[1][1], a1, b1);
                    fma2(acc[2][0], a2, b0); fma2(acc[2][1], a2, b1);
                    fma2(acc[3][0], a3, b0); fma2(acc[3][1], a3, b1);
                }
#pragma unroll
                for (int rp = 0; rp < 4; rp++) {
                    float2 v0 = unp(acc[rp][0]), v1 = unp(acc[rp][1]);
                    int row = gr0 + 2 * rp;
                    *(float2*)(g_gp + (size_t)(sp * NB + row) * 3072 + ct * 128 + gc0) =
                        make_float2(v0.x, v1.x);
                    *(float2*)(g_gp + (size_t)(sp * NB + row + 1) * 3072 + ct * 128 + gc0) =
                        make_float2(v0.y, v1.y);
                }
            }
            gbar(sense);

            // ===== phase C: stats assembly + gates + mem-LN =====
            if (bid < NB) {
                int b = bid, m = tid;
                float gs[6];
#pragma unroll
                for (int c = 0; c < 6; c++) {
                    float s = 0.f;
#pragma unroll
                    for (int sp = 0; sp < 4; sp++)
                        s += g_gp[(size_t)(sp * NB + b) * 3072 + c * 512 + m];
                    gs[c] = s;
                }
                float ho = hoth[b * NM + m];
                float hs = hslf[b * NM + m];
                float ph  = g_p1[l * NM + m] * ho;
                float aph = ((l == 0) ? g_aP[((size_t)b * NT + t) * NM + m] : g_aP1c[m]) * ho;
                float hqh = gs[5] * ho;
#pragma unroll
                for (int off = 16; off > 0; off >>= 1) {
                    ph  += __shfl_xor_sync(0xffffffffu, ph, off);
                    aph += __shfl_xor_sync(0xffffffffu, aph, off);
                    hqh += __shfl_xor_sync(0xffffffffu, hqh, off);
                }
                int w = tid >> 5;
                if ((tid & 31) == 0) { sRed[w] = ph; sRed[16 + w] = aph; sRed[32 + w] = hqh; }
                __syncthreads();
                if (tid == 0) {
                    float t0 = 0.f, t1 = 0.f, t2 = 0.f;
#pragma unroll
                    for (int i = 0; i < 16; i++) { t0 += sRed[i]; t1 += sRed[16 + i]; t2 += sRed[32 + i]; }
                    sOut[0] = t0; sOut[1] = t1; sOut[2] = t2;
                }
                __syncthreads();
                float S1, S2, fbf = 1.f;
                if (l == 0) {
                    if (t == 0) { S1 = g_A1z[b]; S2 = g_A2z[b]; fbf = 0.f; }
                    else {
                        S1 = g_A1[(size_t)b * NT + t] + sOut[0];
                        S2 = g_A2[(size_t)b * NT + t] + 2.f * sOut[1] + sOut[2];
                    }
                } else {
                    S1 = g_c12[0] + sOut[0];
                    S2 = g_c12[1] + 2.f * sOut[1] + sOut[2];
                }
                float mu = S1 * (1.f / NH);
                float ri = rsqrtf(S2 * (1.f / NH) - mu * mu + 1e-5f);
                float Xu, Xr, Xc;
                if (l == 0) {
                    const float* xb = g_X0 + ((size_t)b * NT + t) * 1536;
                    Xu = xb[m]; Xr = xb[512 + m]; Xc = xb[1024 + m];
                    if (t == 0) { Xu -= g_fbadj[m]; Xr -= g_fbadj[512 + m]; Xc -= g_fbadj[1024 + m]; }
                } else {
                    Xu = g_cv1[m]; Xr = g_cv1[512 + m]; Xc = g_cv1[1024 + m];
                }
                int cb = l * 1536;
                float pu = ri * (Xu + fbf * gs[0] - mu * g_cs[cb + m])        + g_dv[cb + m]        + gs[3];
                float pr = ri * (Xr + fbf * gs[1] - mu * g_cs[cb + 512 + m])  + g_dv[cb + 512 + m]  + gs[4];
                float pc = ri * (Xc + fbf * gs[2] - mu * g_cs[cb + 1024 + m]) + g_dv[cb + 1024 + m];
                float u = 1.f / (1.f + expf(-pu));
                float r = 1.f / (1.f + expf(-pr));
                float cand = tanhf(pc);
                float d = g_dcoef[l * NM + m] * u;
                float hn = d * (hs * r) + (1.f - d) * cand;
                float s1 = hn, s2 = hn * hn;
#pragma unroll
                for (int off = 16; off > 0; off >>= 1) {
                    s1 += __shfl_xor_sync(0xffffffffu, s1, off);
                    s2 += __shfl_xor_sync(0xffffffffu, s2, off);
                }
                if ((tid & 31) == 0) { sRed[w] = s1; sRed[16 + w] = s2; }
                __syncthreads();
                if (tid == 0) {
                    float t1 = 0.f, t2 = 0.f;
#pragma unroll
                    for (int i = 0; i < 16; i++) { t1 += sRed[i]; t2 += sRed[16 + i]; }
                    float mu2 = t1 * (1.f / NM);
                    sOut[3] = mu2;
                    sOut[4] = rsqrtf(t2 * (1.f / NM) - mu2 * mu2 + 1e-5f);
                }
                __syncthreads();
                float vv = (hn - sOut[3]) * sOut[4] * mn_w[l * NM + m] + mn_b[l * NM + m];
                g_h[(size_t)(l * NB + b) * NM + m] = vv;
                if (l == 1) out[((size_t)b * NT + t) * NM + m] = vv;
            }
            gbar(sense);
        }
    }

    // ---- final hidden states hT appended after outs [B,T,M] ----
    for (int i = bid * NTHR + tid; i < 2 * NB * NM; i += NBLK * NTHR)
        out[(size_t)NB * NT * NM + i] = g_h[i];
}

extern "C" void kernel_launch(void* const* d_in, const int* in_sizes, int n_in,
                              void* d_out, int out_size)
{
    const float* x      = (const float*)d_in[0];
    const float* hidden = (const float*)d_in[1];
    const float* W_in   = (const float*)d_in[2];
    const float* b_in   = (const float*)d_in[3];
    const float* cell_W = (const float*)d_in[4];
    const float* cell_b = (const float*)d_in[5];
    const float* upd_W  = (const float*)d_in[6];
    const float* upd_b  = (const float*)d_in[7];
    const float* rst_W  = (const float*)d_in[8];
    const float* rst_b  = (const float*)d_in[9];
    const float* tau    = (const float*)d_in[10];
    const float* lc_W   = (const float*)d_in[11];
    const float* lc_b   = (const float*)d_in[12];
    const float* sk_W   = (const float*)d_in[13];
    const float* sk_b   = (const float*)d_in[14];
    const float* fb_W   = (const float*)d_in[15];
    const float* fb_b   = (const float*)d_in[16];
    const float* ln_w   = (const float*)d_in[17];
    const float* ln_b   = (const float*)d_in[18];
    const float* mn_w   = (const float*)d_in[19];
    const float* mn_b   = (const float*)d_in[20];
    float* out = (float*)d_out;

    cudaFuncSetAttribute(ltc_all, cudaFuncAttributeMaxDynamicSharedMemorySize, DYN_BYTES);
    ltc_all<<<NBLK, NTHR, DYN_BYTES>>>(x, hidden, W_in, b_in, cell_W, cell_b,
                                       upd_W, upd_b, rst_W, rst_b, tau,
                                       lc_W, lc_b, sk_W, sk_b, fb_W, fb_b,
                                       ln_w, ln_b, mn_w, mn_b, out);
}